// round 6
// baseline (speedup 1.0000x reference)
#include <cuda_runtime.h>

typedef unsigned int U32;
typedef unsigned short U16;

static __device__ __forceinline__ float mish_f(float x){
    // mish(x) = x * ((1+e^x)^2 - 1) / ((1+e^x)^2 + 1), division via
    // bit-hack reciprocal + 2 Newton iterations (FMA pipe, no MUFU.RCP).
    float e  = __expf(fminf(x, 30.0f));
    float u  = 1.0f + e;
    float u2 = u * u;
    float d  = u2 + 1.0f;
    float r  = __int_as_float(0x7EF311C2 - __float_as_int(d));
    r = r * (2.0f - d * r);
    r = r * (2.0f - d * r);
    return x * (u2 - 1.0f) * r;
}

// g_AB: [pred(3)][half(2)][row(2048)][col(256)]  (P = x@W1_top, Q = x@W1_bot)
__device__ float g_AB[6 * 2048 * 256];
// g_W2h: W2 in fp16, fragment order: [pred(3)][nhalf(2)][chunk(4)][8192 halves]
// within chunk: ((ks*8 + np)*32 + lane)*8 + (odd*2 + hi)*2 + comp
__device__ U16 g_W2h[3 * 65536];

// ---------------------------------------------------------------------------
// w2frag_kernel: W2 -> fp16 fragment layout (N split into halves of 128).
// ---------------------------------------------------------------------------
__global__ __launch_bounds__(256) void w2frag_kernel(
    const float* __restrict__ W2a,
    const float* __restrict__ W2b,
    const float* __restrict__ W2c)
{
    int idx = blockIdx.x * 256 + threadIdx.x;   // 0 .. 196607
    int p = idx >> 16;
    int rem = idx & 65535;
    int k = rem >> 8, n = rem & 255;
    const float* W2 = (p == 0) ? W2a : (p == 1) ? W2b : W2c;
    float v = W2[k * 256 + n];
    U16 hv;
    asm("{ .reg .f16 t; cvt.rn.f16.f32 t, %1; mov.b16 %0, t; }" : "=h"(hv) : "f"(v));
    int c = k >> 6, kk = k & 63;
    int ks = kk >> 4, r = kk & 15;
    int hi = r >> 3, r8 = r & 7, tl = r8 >> 1, comp = r8 & 1;
    int nhalf = n >> 7, nl = n & 127;
    int nt = nl >> 3, np = nt >> 1, odd = nt & 1, g = nl & 7;
    int lane = g * 4 + tl;
    int halfidx = ((ks * 8 + np) * 32 + lane) * 8 + (odd * 2 + hi) * 2 + comp;
    g_W2h[((p * 2 + nhalf) * 4 + c) * 8192 + halfidx] = hv;
}

// ---------------------------------------------------------------------------
// ab_kernel: P = x @ W1[:128,:], Q = x @ W1[128:,:] for each of 3 predicates.
// ---------------------------------------------------------------------------
__global__ __launch_bounds__(256) void ab_kernel(
    const float* __restrict__ emb,
    const float* __restrict__ W1a,
    const float* __restrict__ W1b,
    const float* __restrict__ W1c)
{
    __shared__ float Xs[16][65];
    __shared__ float Ws[16][64];
    int z = blockIdx.z;
    int p = z >> 1, half = z & 1;
    const float* W = (p == 0 ? W1a : (p == 1 ? W1b : W1c)) + half * 128 * 256;
    int row0 = blockIdx.y * 64;
    int col0 = blockIdx.x * 64;
    int tid = threadIdx.x;
    int tr = tid >> 4, tc = tid & 15;
    float acc[4][4];
    #pragma unroll
    for (int r = 0; r < 4; r++)
        #pragma unroll
        for (int c = 0; c < 4; c++) acc[r][c] = 0.0f;

    for (int k0 = 0; k0 < 128; k0 += 16){
        int kx = tid & 15, rx = tid >> 4;
        #pragma unroll
        for (int pp = 0; pp < 4; pp++)
            Xs[kx][rx + pp*16] = emb[(row0 + rx + pp*16)*128 + k0 + kx];
        int cw = tid & 63, kw = tid >> 6;
        #pragma unroll
        for (int pp = 0; pp < 4; pp++)
            Ws[kw + pp*4][cw] = W[(k0 + kw + pp*4)*256 + col0 + cw];
        __syncthreads();
        #pragma unroll
        for (int k = 0; k < 16; k++){
            float a[4], bv[4];
            #pragma unroll
            for (int r = 0; r < 4; r++) a[r] = Xs[k][tr*4 + r];
            #pragma unroll
            for (int c = 0; c < 4; c++) bv[c] = Ws[k][tc*4 + c];
            #pragma unroll
            for (int r = 0; r < 4; r++)
                #pragma unroll
                for (int c = 0; c < 4; c++)
                    acc[r][c] = fmaf(a[r], bv[c], acc[r][c]);
        }
        __syncthreads();
    }
    float* out = g_AB + (size_t)z * 2048 * 256;
    #pragma unroll
    for (int r = 0; r < 4; r++){
        float4 v = make_float4(acc[r][0], acc[r][1], acc[r][2], acc[r][3]);
        *(float4*)&out[(row0 + tr*4 + r)*256 + col0 + tc*4] = v;
    }
}

// ---------------------------------------------------------------------------
// p0_kernel: arity-1 residual MLP.
// ---------------------------------------------------------------------------
__global__ __launch_bounds__(256) void p0_kernel(
    const float* __restrict__ emb,
    const float* __restrict__ W1,
    const float* __restrict__ b1,
    const float* __restrict__ W2,
    const float* __restrict__ b2,
    float* __restrict__ out)
{
    __shared__ float buf[128][65];
    __shared__ float wch[16][128];
    __shared__ float bias[128];
    int row0 = blockIdx.x * 64;
    int tid = threadIdx.x;
    int tr = tid >> 5, tc = tid & 31;

    for (int idx = tid; idx < 64*128; idx += 256){
        int k = idx & 127, r = idx >> 7;
        buf[k][r] = emb[(row0 + r)*128 + k];
    }
    if (tid < 128) bias[tid] = b1[tid];
    __syncthreads();

    float acc[8][4];
    #pragma unroll
    for (int r = 0; r < 8; r++)
        #pragma unroll
        for (int c = 0; c < 4; c++) acc[r][c] = 0.0f;

    for (int k0 = 0; k0 < 128; k0 += 16){
        #pragma unroll
        for (int pp = 0; pp < 8; pp++){
            int idx = tid + pp*256;
            int c = idx & 127, kk = idx >> 7;
            wch[kk][c] = W1[(k0 + kk)*128 + c];
        }
        __syncthreads();
        #pragma unroll
        for (int k = 0; k < 16; k++){
            float a[8], bv[4];
            #pragma unroll
            for (int r = 0; r < 8; r++) a[r] = buf[k0 + k][tr*8 + r];
            #pragma unroll
            for (int c = 0; c < 4; c++) bv[c] = wch[k][tc*4 + c];
            #pragma unroll
            for (int r = 0; r < 8; r++)
                #pragma unroll
                for (int c = 0; c < 4; c++)
                    acc[r][c] = fmaf(a[r], bv[c], acc[r][c]);
        }
        __syncthreads();
    }

    float hval[8][4];
    #pragma unroll
    for (int r = 0; r < 8; r++)
        #pragma unroll
        for (int c = 0; c < 4; c++)
            hval[r][c] = mish_f(acc[r][c] + bias[tc*4 + c]);
    __syncthreads();
    #pragma unroll
    for (int r = 0; r < 8; r++)
        #pragma unroll
        for (int c = 0; c < 4; c++)
            buf[tc*4 + c][tr*8 + r] = hval[r][c];
    if (tid < 128) bias[tid] = b2[tid];

    float acc2[8][4];
    #pragma unroll
    for (int r = 0; r < 8; r++)
        #pragma unroll
        for (int c = 0; c < 4; c++) acc2[r][c] = 0.0f;

    for (int k0 = 0; k0 < 128; k0 += 16){
        #pragma unroll
        for (int pp = 0; pp < 8; pp++){
            int idx = tid + pp*256;
            int c = idx & 127, kk = idx >> 7;
            wch[kk][c] = W2[(k0 + kk)*128 + c];
        }
        __syncthreads();
        #pragma unroll
        for (int k = 0; k < 16; k++){
            float a[8], bv[4];
            #pragma unroll
            for (int r = 0; r < 8; r++) a[r] = buf[k0 + k][tr*8 + r];
            #pragma unroll
            for (int c = 0; c < 4; c++) bv[c] = wch[k][tc*4 + c];
            #pragma unroll
            for (int r = 0; r < 8; r++)
                #pragma unroll
                for (int c = 0; c < 4; c++)
                    acc2[r][c] = fmaf(a[r], bv[c], acc2[r][c]);
        }
        __syncthreads();
    }

    #pragma unroll
    for (int r = 0; r < 8; r++){
        int row = row0 + tr*8 + r;
        float4 x = *(const float4*)&emb[row*128 + tc*4];
        float4 o = make_float4(x.x + acc2[r][0] + bias[tc*4+0],
                               x.y + acc2[r][1] + bias[tc*4+1],
                               x.z + acc2[r][2] + bias[tc*4+2],
                               x.w + acc2[r][3] + bias[tc*4+3]);
        *(float4*)&out[row*128 + tc*4] = o;
    }
}

// ---------------------------------------------------------------------------
// pair_mma_kernel: arity-2 via fp16 mma.sync (m16n8k16, f32 acc).
// Block = (pred p, state b, object i, N-half): 256 threads, 8 warps (2M x 4N),
// warp tile 32x32, acc[2][4][4] = 32 regs. GEMM: M=64 (j rows), N=128, K=256
// in 4 chunks of 64. 2 CTAs/SM.
// SMEM bytes: A0[0,8192) A1[8192,16384) B0[16384,32768) B1[32768,49152)
//             av[49152,50176) xi[50176,50688) b2[50688,51200)
// Epilogue (nhalf=1): xj[64][132] floats overlaid at offset 0 (132 % 4 == 0
// keeps the float4 staging stores 16B-aligned).
// ---------------------------------------------------------------------------
#define PAIR_SMEM_BYTES 51200

#define MMA_F16(d, a, b0v, b1v) \
    asm volatile("mma.sync.aligned.m16n8k16.row.col.f32.f16.f16.f32 " \
        "{%0,%1,%2,%3}, {%4,%5,%6,%7}, {%8,%9}, {%0,%1,%2,%3};" \
        : "+f"(d[0]), "+f"(d[1]), "+f"(d[2]), "+f"(d[3]) \
        : "r"((a).x), "r"((a).y), "r"((a).z), "r"((a).w), \
          "r"(b0v), "r"(b1v))

static __device__ __forceinline__ U32 pack_h2(float lo, float hi){
    U32 r;
    asm("cvt.rn.f16x2.f32 %0, %1, %2;" : "=r"(r) : "f"(hi), "f"(lo));
    return r;
}

static __device__ __forceinline__ void cp16(U32 dst, const void* src){
    asm volatile("cp.async.cg.shared.global [%0], [%1], 16;"
                 :: "r"(dst), "l"(src) : "memory");
}

__global__ __launch_bounds__(256, 2) void pair_mma_kernel(
    const float* __restrict__ emb,
    const float* __restrict__ b1a, const float* __restrict__ b1b, const float* __restrict__ b1c,
    const float* __restrict__ b2a, const float* __restrict__ b2b, const float* __restrict__ b2c,
    float* __restrict__ outbase)
{
    extern __shared__ char smc[];
    float* av   = (float*)(smc + 49152);
    float* xi_s = (float*)(smc + 50176);
    float* b2_s = (float*)(smc + 50688);
    U32 smem32;
    asm("{ .reg .u64 t; cvta.to.shared.u64 t, %1; cvt.u32.u64 %0, t; }"
        : "=r"(smem32) : "l"(smc));

    int p = blockIdx.y;
    const float* b1 = (p == 0) ? b1a : (p == 1) ? b1b : b1c;
    const float* b2 = (p == 0) ? b2a : (p == 1) ? b2b : b2c;
    float* outp = outbase + (size_t)p * 33554432;

    int bx = blockIdx.x;
    int nhalf = bx & 1;
    int ti = bx >> 1;                 // 0..2047 = b*64 + i
    int b = ti >> 6;
    const float* Pi = g_AB + ((size_t)(p*2) * 2048 + (size_t)ti) * 256;
    const float* Q  = g_AB + ((size_t)(p*2 + 1) * 2048 + (size_t)(b*64)) * 256;
    const uint4* Wsrc = (const uint4*)g_W2h + (size_t)(p*2 + nhalf) * 4096;

    int t = threadIdx.x;
    int wid = t >> 5, lane = t & 31;
    int wm = wid & 1, wn = wid >> 1;
    int g = lane >> 2, tl = lane & 3;

    // av[k] = P[i][k] + b1[k]; stage xi (nhalf=0) and b2 half
    av[t] = Pi[t] + b1[t];
    if (t < 32){
        if (nhalf == 0){
            float4 v = ((const float4*)(emb + (size_t)ti * 128))[t];
            *(float4*)&xi_s[t*4] = v;
        }
        float4 bv = ((const float4*)(b2 + nhalf*128))[t];
        *(float4*)&b2_s[t*4] = bv;
    }
    __syncthreads();

    // W2 chunk async copy: 16KB = 1024 uint4, 4 per thread
    auto produceW = [&](int c, U32 Bs32){
        const uint4* src = Wsrc + c * 1024 + t;
        #pragma unroll
        for (int it = 0; it < 4; it++)
            cp16(Bs32 + (U32)(t + it*256) * 16u, src + it*256);
        asm volatile("cp.async.commit_group;" ::: "memory");
    };

    // A (h) fragments: 512 uint4 per chunk, 2 per thread, exact mma layout
    auto produceA = [&](int c, char* Ab){
        #pragma unroll
        for (int e = 0; e < 2; e++){
            int idx = t + e*256;
            int ks = idx >> 7;
            int mt = (idx >> 5) & 3;
            int ln = idx & 31;
            int gg = ln >> 2, tll = ln & 3;
            int j = mt*16 + gg;
            int kb = c*64 + ks*16 + 2*tll;
            const float* qr0 = Q + (size_t)j * 256 + kb;
            const float* qr1 = qr0 + 8 * 256;
            float2 qa0 = *(const float2*)qr0;
            float2 qa1 = *(const float2*)(qr0 + 8);
            float2 qb0 = *(const float2*)qr1;
            float2 qb1 = *(const float2*)(qr1 + 8);
            float2 av0 = *(const float2*)(av + kb);
            float2 av1 = *(const float2*)(av + kb + 8);
            U32 a0 = pack_h2(mish_f(av0.x + qa0.x), mish_f(av0.y + qa0.y));
            U32 a1 = pack_h2(mish_f(av0.x + qb0.x), mish_f(av0.y + qb0.y));
            U32 a2 = pack_h2(mish_f(av1.x + qa1.x), mish_f(av1.y + qa1.y));
            U32 a3 = pack_h2(mish_f(av1.x + qb1.x), mish_f(av1.y + qb1.y));
            *(uint4*)(Ab + (((ks*4 + mt)*32 + ln) << 4)) = make_uint4(a0,a1,a2,a3);
        }
    };

    float acc[2][4][4];
    #pragma unroll
    for (int mf = 0; mf < 2; mf++)
        #pragma unroll
        for (int nf = 0; nf < 4; nf++)
            #pragma unroll
            for (int u = 0; u < 4; u++) acc[mf][nf][u] = 0.0f;

    auto consume = [&](char* Ab, char* Bb){
        #pragma unroll
        for (int ks = 0; ks < 4; ks++){
            uint4 aA = *(uint4*)(Ab + (((ks*4 + wm*2    )*32 + lane) << 4));
            uint4 aB = *(uint4*)(Ab + (((ks*4 + wm*2 + 1)*32 + lane) << 4));
            #pragma unroll
            for (int npp = 0; npp < 2; npp++){
                uint4 v = *(uint4*)(Bb + (((ks*8 + wn*2 + npp)*32 + lane) << 4));
                MMA_F16(acc[0][2*npp    ], aA, v.x, v.y);
                MMA_F16(acc[1][2*npp    ], aB, v.x, v.y);
                MMA_F16(acc[0][2*npp + 1], aA, v.z, v.w);
                MMA_F16(acc[1][2*npp + 1], aB, v.z, v.w);
            }
        }
    };

    char* A0 = smc;          char* A1 = smc + 8192;
    char* B0 = smc + 16384;  char* B1 = smc + 32768;
    U32 B0a = smem32 + 16384, B1a = smem32 + 32768;

    produceW(0, B0a); produceA(0, A0);
    asm volatile("cp.async.wait_group 0;" ::: "memory");
    __syncthreads();
    produceW(1, B1a); produceA(1, A1); consume(A0, B0);
    asm volatile("cp.async.wait_group 0;" ::: "memory");
    __syncthreads();
    produceW(2, B0a); produceA(2, A0); consume(A1, B1);
    asm volatile("cp.async.wait_group 0;" ::: "memory");
    __syncthreads();
    produceW(3, B1a); produceA(3, A1); consume(A0, B0);
    asm volatile("cp.async.wait_group 0;" ::: "memory");
    __syncthreads();
    consume(A1, B1);

    // ---- epilogue ----
    float* xj_s = (float*)smc;        // [64][132] (nhalf=1 only), 33792 B fits
    if (nhalf == 1){
        __syncthreads();
        const float* embB = emb + (size_t)(b*64) * 128;
        #pragma unroll
        for (int it = 0; it < 8; it++){
            int idx = t + it*256;
            int jr = idx >> 5, c4 = idx & 31;
            float4 v = ((const float4*)(embB + (size_t)jr*128))[c4];
            *(float4*)&xj_s[jr*132 + c4*4] = v;
        }
    }
    __syncthreads();

    size_t rowbase = (size_t)ti * 64;
    int colbase = nhalf * 128;

    #pragma unroll
    for (int mf = 0; mf < 2; mf++){
        int jr0 = wm*32 + mf*16 + g;
        int jr1 = jr0 + 8;
        float* o0 = outp + (rowbase + jr0) * 256 + colbase;
        float* o1 = outp + (rowbase + jr1) * 256 + colbase;
        #pragma unroll
        for (int nf = 0; nf < 4; nf++){
            int col = wn*32 + nf*8 + 2*tl;
            float add00, add01, add10, add11;
            if (nhalf == 0){
                float x0 = xi_s[col], x1 = xi_s[col + 1];
                add00 = x0; add01 = x1; add10 = x0; add11 = x1;
            } else {
                add00 = xj_s[jr0*132 + col];
                add01 = xj_s[jr0*132 + col + 1];
                add10 = xj_s[jr1*132 + col];
                add11 = xj_s[jr1*132 + col + 1];
            }
            float bb0 = b2_s[col], bb1 = b2_s[col + 1];
            float2 v0 = make_float2(acc[mf][nf][0] + add00 + bb0,
                                    acc[mf][nf][1] + add01 + bb1);
            float2 v1 = make_float2(acc[mf][nf][2] + add10 + bb0,
                                    acc[mf][nf][3] + add11 + bb1);
            *(float2*)&o0[col] = v0;
            *(float2*)&o1[col] = v1;
        }
    }
}

// ---------------------------------------------------------------------------
extern "C" void kernel_launch(void* const* d_in, const int* in_sizes, int n_in,
                              void* d_out, int out_size)
{
    (void)in_sizes; (void)n_in; (void)out_size;
    const float* emb  = (const float*)d_in[0];
    const float* W1_0 = (const float*)d_in[2];
    const float* b1_0 = (const float*)d_in[3];
    const float* W2_0 = (const float*)d_in[4];
    const float* b2_0 = (const float*)d_in[5];
    const float* W1_1 = (const float*)d_in[6];
    const float* b1_1 = (const float*)d_in[7];
    const float* W2_1 = (const float*)d_in[8];
    const float* b2_1 = (const float*)d_in[9];
    const float* W1_2 = (const float*)d_in[10];
    const float* b1_2 = (const float*)d_in[11];
    const float* W2_2 = (const float*)d_in[12];
    const float* b2_2 = (const float*)d_in[13];
    const float* W1_3 = (const float*)d_in[14];
    const float* b1_3 = (const float*)d_in[15];
    const float* W2_3 = (const float*)d_in[16];
    const float* b2_3 = (const float*)d_in[17];
    float* out = (float*)d_out;

    static int smem_set = 0;
    if (!smem_set){
        cudaFuncSetAttribute(pair_mma_kernel,
                             cudaFuncAttributeMaxDynamicSharedMemorySize,
                             PAIR_SMEM_BYTES);
        smem_set = 1;
    }

    w2frag_kernel<<<768, 256>>>(W2_1, W2_2, W2_3);
    ab_kernel<<<dim3(4, 32, 6), 256>>>(emb, W1_1, W1_2, W1_3);
    p0_kernel<<<32, 256>>>(emb, W1_0, b1_0, W2_0, b2_0, out);
    pair_mma_kernel<<<dim3(4096, 3), 256, PAIR_SMEM_BYTES>>>(
        emb,
        b1_1, b1_2, b1_3,
        b2_1, b2_2, b2_3,
        out + 262144);
}

// round 7
// speedup vs baseline: 1.0996x; 1.0996x over previous
#include <cuda_runtime.h>

typedef unsigned int U32;
typedef unsigned short U16;

static __device__ __forceinline__ float mish_f(float x){
    // mish(x) = x * ((1+e^x)^2 - 1) / ((1+e^x)^2 + 1), division via
    // bit-hack reciprocal + 2 Newton iterations (FMA pipe, no MUFU.RCP).
    float e  = __expf(fminf(x, 30.0f));
    float u  = 1.0f + e;
    float u2 = u * u;
    float d  = u2 + 1.0f;
    float r  = __int_as_float(0x7EF311C2 - __float_as_int(d));
    r = r * (2.0f - d * r);
    r = r * (2.0f - d * r);
    return x * (u2 - 1.0f) * r;
}

// g_AB: [pred(3)][half(2)][row(2048)][col(256)]  (P = x@W1_top, Q = x@W1_bot)
__device__ float g_AB[6 * 2048 * 256];
// g_W2h: W2 in fp16, fragment order: [pred(3)][nhalf(2)][chunk(4)][8192 halves]
// within chunk: ((ks*8 + np)*32 + lane)*8 + (odd*2 + hi)*2 + comp
__device__ U16 g_W2h[3 * 65536];

// ---------------------------------------------------------------------------
// w2frag_kernel: W2 -> fp16 fragment layout (N split into halves of 128).
// ---------------------------------------------------------------------------
__global__ __launch_bounds__(256) void w2frag_kernel(
    const float* __restrict__ W2a,
    const float* __restrict__ W2b,
    const float* __restrict__ W2c)
{
    int idx = blockIdx.x * 256 + threadIdx.x;   // 0 .. 196607
    int p = idx >> 16;
    int rem = idx & 65535;
    int k = rem >> 8, n = rem & 255;
    const float* W2 = (p == 0) ? W2a : (p == 1) ? W2b : W2c;
    float v = W2[k * 256 + n];
    U16 hv;
    asm("{ .reg .f16 t; cvt.rn.f16.f32 t, %1; mov.b16 %0, t; }" : "=h"(hv) : "f"(v));
    int c = k >> 6, kk = k & 63;
    int ks = kk >> 4, r = kk & 15;
    int hi = r >> 3, r8 = r & 7, tl = r8 >> 1, comp = r8 & 1;
    int nhalf = n >> 7, nl = n & 127;
    int nt = nl >> 3, np = nt >> 1, odd = nt & 1, g = nl & 7;
    int lane = g * 4 + tl;
    int halfidx = ((ks * 8 + np) * 32 + lane) * 8 + (odd * 2 + hi) * 2 + comp;
    g_W2h[((p * 2 + nhalf) * 4 + c) * 8192 + halfidx] = hv;
}

// ---------------------------------------------------------------------------
// ab_kernel: P = x @ W1[:128,:], Q = x @ W1[128:,:] for each of 3 predicates.
// ---------------------------------------------------------------------------
__global__ __launch_bounds__(256) void ab_kernel(
    const float* __restrict__ emb,
    const float* __restrict__ W1a,
    const float* __restrict__ W1b,
    const float* __restrict__ W1c)
{
    __shared__ float Xs[16][65];
    __shared__ float Ws[16][64];
    int z = blockIdx.z;
    int p = z >> 1, half = z & 1;
    const float* W = (p == 0 ? W1a : (p == 1 ? W1b : W1c)) + half * 128 * 256;
    int row0 = blockIdx.y * 64;
    int col0 = blockIdx.x * 64;
    int tid = threadIdx.x;
    int tr = tid >> 4, tc = tid & 15;
    float acc[4][4];
    #pragma unroll
    for (int r = 0; r < 4; r++)
        #pragma unroll
        for (int c = 0; c < 4; c++) acc[r][c] = 0.0f;

    for (int k0 = 0; k0 < 128; k0 += 16){
        int kx = tid & 15, rx = tid >> 4;
        #pragma unroll
        for (int pp = 0; pp < 4; pp++)
            Xs[kx][rx + pp*16] = emb[(row0 + rx + pp*16)*128 + k0 + kx];
        int cw = tid & 63, kw = tid >> 6;
        #pragma unroll
        for (int pp = 0; pp < 4; pp++)
            Ws[kw + pp*4][cw] = W[(k0 + kw + pp*4)*256 + col0 + cw];
        __syncthreads();
        #pragma unroll
        for (int k = 0; k < 16; k++){
            float a[4], bv[4];
            #pragma unroll
            for (int r = 0; r < 4; r++) a[r] = Xs[k][tr*4 + r];
            #pragma unroll
            for (int c = 0; c < 4; c++) bv[c] = Ws[k][tc*4 + c];
            #pragma unroll
            for (int r = 0; r < 4; r++)
                #pragma unroll
                for (int c = 0; c < 4; c++)
                    acc[r][c] = fmaf(a[r], bv[c], acc[r][c]);
        }
        __syncthreads();
    }
    float* out = g_AB + (size_t)z * 2048 * 256;
    #pragma unroll
    for (int r = 0; r < 4; r++){
        float4 v = make_float4(acc[r][0], acc[r][1], acc[r][2], acc[r][3]);
        *(float4*)&out[(row0 + tr*4 + r)*256 + col0 + tc*4] = v;
    }
}

// ---------------------------------------------------------------------------
// p0_kernel: arity-1 residual MLP.
// ---------------------------------------------------------------------------
__global__ __launch_bounds__(256) void p0_kernel(
    const float* __restrict__ emb,
    const float* __restrict__ W1,
    const float* __restrict__ b1,
    const float* __restrict__ W2,
    const float* __restrict__ b2,
    float* __restrict__ out)
{
    __shared__ float buf[128][65];
    __shared__ float wch[16][128];
    __shared__ float bias[128];
    int row0 = blockIdx.x * 64;
    int tid = threadIdx.x;
    int tr = tid >> 5, tc = tid & 31;

    for (int idx = tid; idx < 64*128; idx += 256){
        int k = idx & 127, r = idx >> 7;
        buf[k][r] = emb[(row0 + r)*128 + k];
    }
    if (tid < 128) bias[tid] = b1[tid];
    __syncthreads();

    float acc[8][4];
    #pragma unroll
    for (int r = 0; r < 8; r++)
        #pragma unroll
        for (int c = 0; c < 4; c++) acc[r][c] = 0.0f;

    for (int k0 = 0; k0 < 128; k0 += 16){
        #pragma unroll
        for (int pp = 0; pp < 8; pp++){
            int idx = tid + pp*256;
            int c = idx & 127, kk = idx >> 7;
            wch[kk][c] = W1[(k0 + kk)*128 + c];
        }
        __syncthreads();
        #pragma unroll
        for (int k = 0; k < 16; k++){
            float a[8], bv[4];
            #pragma unroll
            for (int r = 0; r < 8; r++) a[r] = buf[k0 + k][tr*8 + r];
            #pragma unroll
            for (int c = 0; c < 4; c++) bv[c] = wch[k][tc*4 + c];
            #pragma unroll
            for (int r = 0; r < 8; r++)
                #pragma unroll
                for (int c = 0; c < 4; c++)
                    acc[r][c] = fmaf(a[r], bv[c], acc[r][c]);
        }
        __syncthreads();
    }

    float hval[8][4];
    #pragma unroll
    for (int r = 0; r < 8; r++)
        #pragma unroll
        for (int c = 0; c < 4; c++)
            hval[r][c] = mish_f(acc[r][c] + bias[tc*4 + c]);
    __syncthreads();
    #pragma unroll
    for (int r = 0; r < 8; r++)
        #pragma unroll
        for (int c = 0; c < 4; c++)
            buf[tc*4 + c][tr*8 + r] = hval[r][c];
    if (tid < 128) bias[tid] = b2[tid];

    float acc2[8][4];
    #pragma unroll
    for (int r = 0; r < 8; r++)
        #pragma unroll
        for (int c = 0; c < 4; c++) acc2[r][c] = 0.0f;

    for (int k0 = 0; k0 < 128; k0 += 16){
        #pragma unroll
        for (int pp = 0; pp < 8; pp++){
            int idx = tid + pp*256;
            int c = idx & 127, kk = idx >> 7;
            wch[kk][c] = W2[(k0 + kk)*128 + c];
        }
        __syncthreads();
        #pragma unroll
        for (int k = 0; k < 16; k++){
            float a[8], bv[4];
            #pragma unroll
            for (int r = 0; r < 8; r++) a[r] = buf[k0 + k][tr*8 + r];
            #pragma unroll
            for (int c = 0; c < 4; c++) bv[c] = wch[k][tc*4 + c];
            #pragma unroll
            for (int r = 0; r < 8; r++)
                #pragma unroll
                for (int c = 0; c < 4; c++)
                    acc2[r][c] = fmaf(a[r], bv[c], acc2[r][c]);
        }
        __syncthreads();
    }

    #pragma unroll
    for (int r = 0; r < 8; r++){
        int row = row0 + tr*8 + r;
        float4 x = *(const float4*)&emb[row*128 + tc*4];
        float4 o = make_float4(x.x + acc2[r][0] + bias[tc*4+0],
                               x.y + acc2[r][1] + bias[tc*4+1],
                               x.z + acc2[r][2] + bias[tc*4+2],
                               x.w + acc2[r][3] + bias[tc*4+3]);
        *(float4*)&out[row*128 + tc*4] = o;
    }
}

// ---------------------------------------------------------------------------
// pair_mma_kernel: arity-2 via fp16 mma.sync (m16n8k16, f32 acc).
// Block = (pred p, state b, object i, N-half): 256 threads, 8 warps (2M x 4N),
// warp tile 32x32, acc[2][4][4] = 32 regs. GEMM: M=64 (j rows), N=128, K=256
// in 4 chunks of 64. __launch_bounds__(256,3): 85-reg cap -> 3 CTAs/SM,
// 24 resident warps (the round-6 (256,2) variant still had only 16).
// SMEM bytes: A0[0,8192) A1[8192,16384) B0[16384,32768) B1[32768,49152)
//             av[49152,50176) xi[50176,50688) b2[50688,51200)
// Epilogue (nhalf=1): xj[64][132] floats overlaid at offset 0 (132 % 4 == 0
// keeps the float4 staging stores 16B-aligned).
// ---------------------------------------------------------------------------
#define PAIR_SMEM_BYTES 51200

#define MMA_F16(d, a, b0v, b1v) \
    asm volatile("mma.sync.aligned.m16n8k16.row.col.f32.f16.f16.f32 " \
        "{%0,%1,%2,%3}, {%4,%5,%6,%7}, {%8,%9}, {%0,%1,%2,%3};" \
        : "+f"(d[0]), "+f"(d[1]), "+f"(d[2]), "+f"(d[3]) \
        : "r"((a).x), "r"((a).y), "r"((a).z), "r"((a).w), \
          "r"(b0v), "r"(b1v))

static __device__ __forceinline__ U32 pack_h2(float lo, float hi){
    U32 r;
    asm("cvt.rn.f16x2.f32 %0, %1, %2;" : "=r"(r) : "f"(hi), "f"(lo));
    return r;
}

static __device__ __forceinline__ void cp16(U32 dst, const void* src){
    asm volatile("cp.async.cg.shared.global [%0], [%1], 16;"
                 :: "r"(dst), "l"(src) : "memory");
}

__global__ __launch_bounds__(256, 3) void pair_mma_kernel(
    const float* __restrict__ emb,
    const float* __restrict__ b1a, const float* __restrict__ b1b, const float* __restrict__ b1c,
    const float* __restrict__ b2a, const float* __restrict__ b2b, const float* __restrict__ b2c,
    float* __restrict__ outbase)
{
    extern __shared__ char smc[];
    float* av   = (float*)(smc + 49152);
    float* xi_s = (float*)(smc + 50176);
    float* b2_s = (float*)(smc + 50688);
    U32 smem32;
    asm("{ .reg .u64 t; cvta.to.shared.u64 t, %1; cvt.u32.u64 %0, t; }"
        : "=r"(smem32) : "l"(smc));

    int p = blockIdx.y;
    const float* b1 = (p == 0) ? b1a : (p == 1) ? b1b : b1c;
    const float* b2 = (p == 0) ? b2a : (p == 1) ? b2b : b2c;
    float* outp = outbase + (size_t)p * 33554432;

    int bx = blockIdx.x;
    int nhalf = bx & 1;
    int ti = bx >> 1;                 // 0..2047 = b*64 + i
    int b = ti >> 6;
    const float* Pi = g_AB + ((size_t)(p*2) * 2048 + (size_t)ti) * 256;
    const float* Q  = g_AB + ((size_t)(p*2 + 1) * 2048 + (size_t)(b*64)) * 256;
    const uint4* Wsrc = (const uint4*)g_W2h + (size_t)(p*2 + nhalf) * 4096;

    int t = threadIdx.x;
    int wid = t >> 5, lane = t & 31;
    int wm = wid & 1, wn = wid >> 1;
    int g = lane >> 2, tl = lane & 3;

    // av[k] = P[i][k] + b1[k]; stage xi (nhalf=0) and b2 half
    av[t] = Pi[t] + b1[t];
    if (t < 32){
        if (nhalf == 0){
            float4 v = ((const float4*)(emb + (size_t)ti * 128))[t];
            *(float4*)&xi_s[t*4] = v;
        }
        float4 bv = ((const float4*)(b2 + nhalf*128))[t];
        *(float4*)&b2_s[t*4] = bv;
    }
    __syncthreads();

    // W2 chunk async copy: 16KB = 1024 uint4, 4 per thread
    auto produceW = [&](int c, U32 Bs32){
        const uint4* src = Wsrc + c * 1024 + t;
        #pragma unroll
        for (int it = 0; it < 4; it++)
            cp16(Bs32 + (U32)(t + it*256) * 16u, src + it*256);
        asm volatile("cp.async.commit_group;" ::: "memory");
    };

    // A (h) fragments: 512 uint4 per chunk, 2 per thread, exact mma layout
    auto produceA = [&](int c, char* Ab){
        #pragma unroll
        for (int e = 0; e < 2; e++){
            int idx = t + e*256;
            int ks = idx >> 7;
            int mt = (idx >> 5) & 3;
            int ln = idx & 31;
            int gg = ln >> 2, tll = ln & 3;
            int j = mt*16 + gg;
            int kb = c*64 + ks*16 + 2*tll;
            const float* qr0 = Q + (size_t)j * 256 + kb;
            const float* qr1 = qr0 + 8 * 256;
            float2 qa0 = *(const float2*)qr0;
            float2 qa1 = *(const float2*)(qr0 + 8);
            float2 qb0 = *(const float2*)qr1;
            float2 qb1 = *(const float2*)(qr1 + 8);
            float2 av0 = *(const float2*)(av + kb);
            float2 av1 = *(const float2*)(av + kb + 8);
            U32 a0 = pack_h2(mish_f(av0.x + qa0.x), mish_f(av0.y + qa0.y));
            U32 a1 = pack_h2(mish_f(av0.x + qb0.x), mish_f(av0.y + qb0.y));
            U32 a2 = pack_h2(mish_f(av1.x + qa1.x), mish_f(av1.y + qa1.y));
            U32 a3 = pack_h2(mish_f(av1.x + qb1.x), mish_f(av1.y + qb1.y));
            *(uint4*)(Ab + (((ks*4 + mt)*32 + ln) << 4)) = make_uint4(a0,a1,a2,a3);
        }
    };

    float acc[2][4][4];
    #pragma unroll
    for (int mf = 0; mf < 2; mf++)
        #pragma unroll
        for (int nf = 0; nf < 4; nf++)
            #pragma unroll
            for (int u = 0; u < 4; u++) acc[mf][nf][u] = 0.0f;

    auto consume = [&](char* Ab, char* Bb){
        #pragma unroll
        for (int ks = 0; ks < 4; ks++){
            uint4 aA = *(uint4*)(Ab + (((ks*4 + wm*2    )*32 + lane) << 4));
            uint4 aB = *(uint4*)(Ab + (((ks*4 + wm*2 + 1)*32 + lane) << 4));
            #pragma unroll
            for (int npp = 0; npp < 2; npp++){
                uint4 v = *(uint4*)(Bb + (((ks*8 + wn*2 + npp)*32 + lane) << 4));
                MMA_F16(acc[0][2*npp    ], aA, v.x, v.y);
                MMA_F16(acc[1][2*npp    ], aB, v.x, v.y);
                MMA_F16(acc[0][2*npp + 1], aA, v.z, v.w);
                MMA_F16(acc[1][2*npp + 1], aB, v.z, v.w);
            }
        }
    };

    char* A0 = smc;          char* A1 = smc + 8192;
    char* B0 = smc + 16384;  char* B1 = smc + 32768;
    U32 B0a = smem32 + 16384, B1a = smem32 + 32768;

    produceW(0, B0a); produceA(0, A0);
    asm volatile("cp.async.wait_group 0;" ::: "memory");
    __syncthreads();
    produceW(1, B1a); produceA(1, A1); consume(A0, B0);
    asm volatile("cp.async.wait_group 0;" ::: "memory");
    __syncthreads();
    produceW(2, B0a); produceA(2, A0); consume(A1, B1);
    asm volatile("cp.async.wait_group 0;" ::: "memory");
    __syncthreads();
    produceW(3, B1a); produceA(3, A1); consume(A0, B0);
    asm volatile("cp.async.wait_group 0;" ::: "memory");
    __syncthreads();
    consume(A1, B1);

    // ---- epilogue ----
    float* xj_s = (float*)smc;        // [64][132] (nhalf=1 only), 33792 B fits
    if (nhalf == 1){
        __syncthreads();
        const float* embB = emb + (size_t)(b*64) * 128;
        #pragma unroll
        for (int it = 0; it < 8; it++){
            int idx = t + it*256;
            int jr = idx >> 5, c4 = idx & 31;
            float4 v = ((const float4*)(embB + (size_t)jr*128))[c4];
            *(float4*)&xj_s[jr*132 + c4*4] = v;
        }
    }
    __syncthreads();

    size_t rowbase = (size_t)ti * 64;
    int colbase = nhalf * 128;

    #pragma unroll
    for (int mf = 0; mf < 2; mf++){
        int jr0 = wm*32 + mf*16 + g;
        int jr1 = jr0 + 8;
        float* o0 = outp + (rowbase + jr0) * 256 + colbase;
        float* o1 = outp + (rowbase + jr1) * 256 + colbase;
        #pragma unroll
        for (int nf = 0; nf < 4; nf++){
            int col = wn*32 + nf*8 + 2*tl;
            float add00, add01, add10, add11;
            if (nhalf == 0){
                float x0 = xi_s[col], x1 = xi_s[col + 1];
                add00 = x0; add01 = x1; add10 = x0; add11 = x1;
            } else {
                add00 = xj_s[jr0*132 + col];
                add01 = xj_s[jr0*132 + col + 1];
                add10 = xj_s[jr1*132 + col];
                add11 = xj_s[jr1*132 + col + 1];
            }
            float bb0 = b2_s[col], bb1 = b2_s[col + 1];
            float2 v0 = make_float2(acc[mf][nf][0] + add00 + bb0,
                                    acc[mf][nf][1] + add01 + bb1);
            float2 v1 = make_float2(acc[mf][nf][2] + add10 + bb0,
                                    acc[mf][nf][3] + add11 + bb1);
            *(float2*)&o0[col] = v0;
            *(float2*)&o1[col] = v1;
        }
    }
}

// ---------------------------------------------------------------------------
extern "C" void kernel_launch(void* const* d_in, const int* in_sizes, int n_in,
                              void* d_out, int out_size)
{
    (void)in_sizes; (void)n_in; (void)out_size;
    const float* emb  = (const float*)d_in[0];
    const float* W1_0 = (const float*)d_in[2];
    const float* b1_0 = (const float*)d_in[3];
    const float* W2_0 = (const float*)d_in[4];
    const float* b2_0 = (const float*)d_in[5];
    const float* W1_1 = (const float*)d_in[6];
    const float* b1_1 = (const float*)d_in[7];
    const float* W2_1 = (const float*)d_in[8];
    const float* b2_1 = (const float*)d_in[9];
    const float* W1_2 = (const float*)d_in[10];
    const float* b1_2 = (const float*)d_in[11];
    const float* W2_2 = (const float*)d_in[12];
    const float* b2_2 = (const float*)d_in[13];
    const float* W1_3 = (const float*)d_in[14];
    const float* b1_3 = (const float*)d_in[15];
    const float* W2_3 = (const float*)d_in[16];
    const float* b2_3 = (const float*)d_in[17];
    float* out = (float*)d_out;

    static int smem_set = 0;
    if (!smem_set){
        cudaFuncSetAttribute(pair_mma_kernel,
                             cudaFuncAttributeMaxDynamicSharedMemorySize,
                             PAIR_SMEM_BYTES);
        smem_set = 1;
    }

    w2frag_kernel<<<768, 256>>>(W2_1, W2_2, W2_3);
    ab_kernel<<<dim3(4, 32, 6), 256>>>(emb, W1_1, W1_2, W1_3);
    p0_kernel<<<32, 256>>>(emb, W1_0, b1_0, W2_0, b2_0, out);
    pair_mma_kernel<<<dim3(4096, 3), 256, PAIR_SMEM_BYTES>>>(
        emb,
        b1_1, b1_2, b1_3,
        b2_1, b2_2, b2_3,
        out + 262144);
}